// round 14
// baseline (speedup 1.0000x reference)
#include <cuda_runtime.h>
#include <cstdint>
#include <math.h>

// Problem shape (fixed): N=16, T=256, U=128, V=256, blank = V-1.
#define N_  16
#define T_  256
#define U_  128
#define V_  256
#define DD  383             // anti-diagonals d = 0..382
#define DD_PAD 400
#define LOG2E 1.4426950408889634f
#define LN2   0.6931471805599453f
#define FLGS 512            // per-example flag stride (16B-aligned v4 reads)

// Scratch (allocation-free rule: __device__ globals, zero-initialized).
// SHIFTED diagonal-major PROBABILITIES: pb(n,t,u)=exp(blank lp) at
// [n][t+u+1][u]; pe(n,t,u)=exp(emit lp) at [n][t+u+1][u+1]. Unwritten slots
// stay 0.0 = impossible transition. Rows >= 384 are never written (read as 0).
__device__ __align__(16) float g_pb[N_ * DD_PAD * U_];
__device__ __align__(16) float g_pe[N_ * DD_PAD * U_];
__device__ float g_cost[N_];
// Epoch flags: each row flag gains EXACTLY 1 per launch (one release-red per
// gather CTA), so "flag >= ep" is a reset-free ready test across graph replays.
__device__ __align__(16) unsigned g_rowflag [N_ * FLGS];   // [n*FLGS + r]
__device__ unsigned g_costflag[N_];
__device__ unsigned g_dpep    [N_];

// ---- helpers ---------------------------------------------------------------
__device__ __forceinline__ float ex2_fast(float x) {
    float y; asm("ex2.approx.ftz.f32 %0, %1;" : "=f"(y) : "f"(x)); return y;
}
__device__ __forceinline__ unsigned ld_acq_u32(const unsigned* p) {
    unsigned v;
    asm volatile("ld.acquire.gpu.global.u32 %0, [%1];" : "=r"(v) : "l"(p) : "memory");
    return v;
}
__device__ __forceinline__ uint4 ld_acq_v4(const unsigned* p) {
    uint4 v;
    asm volatile("ld.acquire.gpu.global.v4.u32 {%0,%1,%2,%3}, [%4];"
                 : "=r"(v.x), "=r"(v.y), "=r"(v.z), "=r"(v.w) : "l"(p) : "memory");
    return v;
}
__device__ __forceinline__ void red_rel_add1(unsigned* p) {
    asm volatile("red.release.gpu.global.add.u32 [%0], 1;" :: "l"(p) : "memory");
}
__device__ __forceinline__ bool ok4(uint4 f, unsigned ep) {
    return f.x >= ep && f.y >= ep && f.z >= ep && f.w >= ep;
}

// ---------------------------------------------------------------------------
// DP machinery (linear domain, scaled-forward; see R13).
// ---------------------------------------------------------------------------
#define DP_STEP(bv, ev, dcur)                                                 \
    {                                                                         \
        float la = __shfl_up_sync(0xffffffffu, a3, 1);                        \
        float l0 = (tx == 0) ? 0.0f : la;                                     \
        float n0 = fmaf(a0, (bv).x, l0 * (ev).x);                             \
        float n1 = fmaf(a1, (bv).y, a0 * (ev).y);                             \
        float n2 = fmaf(a2, (bv).z, a1 * (ev).z);                             \
        float n3 = fmaf(a3, (bv).w, a2 * (ev).w);                             \
        a0 = n0; a1 = n1; a2 = n2; a3 = n3;                                   \
        if ((dcur) == target && cap) {                                        \
            saved  = (ci == 0) ? n0 : (ci == 1) ? n1 : (ci == 2) ? n2 : n3;   \
            savedG = G;                                                       \
        }                                                                     \
    }

#define ISSUE_ROW(rr)                                                         \
    {                                                                         \
        int _rrc = (rr) < (DD_PAD - 1) ? (rr) : (DD_PAD - 1);                 \
        unsigned _slot = ((unsigned)(rr) & 15u) * (U_ * 4u) + lane_off;       \
        const float* _gb = bl + (size_t)_rrc * U_ + 4 * tx;                   \
        const float* _ge = em + (size_t)_rrc * U_ + 4 * tx;                   \
        asm volatile("cp.async.ca.shared.global [%0], [%1], 16;"              \
                     :: "r"(sb_base + _slot), "l"(_gb));                      \
        asm volatile("cp.async.ca.shared.global [%0], [%1], 16;"              \
                     :: "r"(se_base + _slot), "l"(_ge));                      \
    }

#define DP_PAIR(p)                                                            \
    {                                                                         \
        asm volatile("cp.async.wait_group 6;" ::: "memory");                  \
        ISSUE_ROW(2 * (p) + 15);                                              \
        ISSUE_ROW(2 * (p) + 16);                                              \
        asm volatile("cp.async.commit_group;" ::: "memory");                  \
        const int _d1 = 2 * (p) + 1;                                          \
        {                                                                     \
            const int _s = _d1 & 15;                                          \
            float4 b = *(const float4*)&sb[_s * U_ + 4 * tx];                 \
            float4 e = *(const float4*)&se[_s * U_ + 4 * tx];                 \
            DP_STEP(b, e, _d1);                                               \
        }                                                                     \
        {                                                                     \
            const int _d2 = _d1 + 1;                                          \
            const int _s = _d2 & 15;                                          \
            float4 b = *(const float4*)&sb[_s * U_ + 4 * tx];                 \
            float4 e = *(const float4*)&se[_s * U_ + 4 * tx];                 \
            DP_STEP(b, e, _d2);                                               \
        }                                                                     \
    }

#define RESCALE_APPLY()                                                       \
    {                                                                         \
        int ef = (int)(mprev >> 23);                                          \
        int k  = 187 - ef;                                                    \
        k = k > 120 ? 120 : (k < -120 ? -120 : k);                            \
        float factor = __uint_as_float((unsigned)(127 + k) << 23);            \
        a0 *= factor; a1 *= factor; a2 *= factor; a3 *= factor;               \
        G += k;                                                               \
    }

#define RESCALE_MEASURE()                                                     \
    {                                                                         \
        float m = fmaxf(fmaxf(a0, a1), fmaxf(a2, a3));                        \
        mprev = __reduce_max_sync(0xffffffffu, __float_as_uint(m));           \
    }

__device__ void dp_warp(const int* __restrict__ lengths,
                        const int* __restrict__ label_lengths,
                        int n, int tx, float* sb, float* se, float* out)
{
    unsigned ep;
    if (tx == 0) ep = atomicAdd(&g_dpep[n], 1u) + 1u;
    ep = __shfl_sync(0xffffffffu, ep, 0);

    const unsigned* flg = g_rowflag + n * FLGS;
    const float* __restrict__ bl = g_pb + (size_t)n * DD_PAD * U_;
    const float* __restrict__ em = g_pe + (size_t)n * DD_PAD * U_;

    const int t_idx  = __ldg(&lengths[n]) - 1;
    const int u_idx  = __ldg(&label_lengths[n]);
    const int target = t_idx + u_idx;

    // alpha scaled by 2^G; seed alpha(0,0)=1 stored as 2^60.
    float a0 = (tx == 0) ? __uint_as_float((127u + 60u) << 23) : 0.0f;
    float a1 = 0.0f, a2 = 0.0f, a3 = 0.0f;
    int   G = 60, savedG = 0;
    float saved = 1.0f;
    const bool cap = (tx == (u_idx >> 2));
    const int  ci  = u_idx & 3;

    const unsigned sb_base = (unsigned)__cvta_generic_to_shared(sb);
    const unsigned se_base = (unsigned)__cvta_generic_to_shared(se);
    const unsigned lane_off = 16u * (unsigned)tx;

    // Initial: wait for rows 1..16 (lane-parallel spins).
    if (tx < 16) {
        while (ld_acq_u32(flg + (tx + 1)) < ep) __nanosleep(64);
    }
    __syncwarp();

    // Prologue: issue rows 1..14 (7 commit groups).
#pragma unroll
    for (int q = 0; q < 7; ++q) {
        ISSUE_ROW(2 * q + 1);
        ISSUE_ROW(2 * q + 2);
        asm volatile("cp.async.commit_group;" ::: "memory");
    }

    unsigned mprev = (127u + 60u) << 23;          // => k = 0 on first apply

    // Group g: pairs 4g..4g+3 (diagonals 8g+1..8g+8; issues rows 8g+15..8g+22);
    // flag check covers rows 8g+12..8g+23, prefetched one group ahead.
    uint4 f0 = ld_acq_v4(flg + 12), f1 = ld_acq_v4(flg + 16), f2 = ld_acq_v4(flg + 20);

    for (int g = 0; g < 45; ++g) {
        while (!(ok4(f0, ep) && ok4(f1, ep) && ok4(f2, ep))) {
            __nanosleep(64);
            int base = 8 * g + 12;
            f0 = ld_acq_v4(flg + base); f1 = ld_acq_v4(flg + base + 4); f2 = ld_acq_v4(flg + base + 8);
        }
        int nbase = (g < 44) ? (8 * g + 20) : 372;
        uint4 nf0 = ld_acq_v4(flg + nbase);
        uint4 nf1 = ld_acq_v4(flg + nbase + 4);
        uint4 nf2 = ld_acq_v4(flg + nbase + 8);

        const int p0 = 4 * g;
        RESCALE_APPLY(); DP_PAIR(p0);     DP_PAIR(p0 + 1); RESCALE_MEASURE();
        RESCALE_APPLY(); DP_PAIR(p0 + 2); DP_PAIR(p0 + 3); RESCALE_MEASURE();

        f0 = nf0; f1 = nf1; f2 = nf2;
    }

    // Tail: confirm rows 372..383, then pairs 180..190.
    while (!(ok4(f0, ep) && ok4(f1, ep) && ok4(f2, ep))) {
        __nanosleep(64);
        f0 = ld_acq_v4(flg + 372); f1 = ld_acq_v4(flg + 376); f2 = ld_acq_v4(flg + 380);
    }
#pragma unroll
    for (int pc = 180; pc < 190; pc += 2) {
        RESCALE_APPLY(); DP_PAIR(pc); DP_PAIR(pc + 1); RESCALE_MEASURE();
    }
    RESCALE_APPLY();
    DP_PAIR(190);   // diagonals 381, 382

    if (cap) {
        float lpb_fin = __log2f(bl[(size_t)(target + 1) * U_ + u_idx]);
        float l2 = __log2f(saved) - (float)savedG + lpb_fin;
        g_cost[n] = -l2 * LN2;
        asm volatile("" ::: "memory");
        __threadfence();
        red_rel_add1(&g_costflag[n]);
    }

    // Finalize (n==0 CTA, lane 0): deterministic serial mean.
    if (n == 0 && tx == 0) {
        float s = 0.0f;
#pragma unroll
        for (int i = 0; i < N_; ++i) {
            while (ld_acq_u32(&g_costflag[i]) < ep) __nanosleep(128);
            s += __ldcg(&g_cost[i]);
        }
        out[0] = s * (1.0f / N_);
    }
}

// ---------------------------------------------------------------------------
// Fused kernel. CTA 0..15: DP warp (example = bid); warps 1..3 exit.
// CTA 16..6143: ONE gather row-task each (identical shape to the proven
// standalone gather: wave-scheduled, coalesced writes, streaming reads),
// plus syncthreads + a single release-red to publish the row flag.
// Gather CTAs never wait -> unconditional completion; DP only waits on flags.
// ---------------------------------------------------------------------------
__global__ void __launch_bounds__(U_) fused_kernel(const float* __restrict__ lp,
                                                   const int*   __restrict__ labels,
                                                   const int*   __restrict__ lengths,
                                                   const int*   __restrict__ label_lengths,
                                                   float* __restrict__ out)
{
    __shared__ __align__(16) float sb[16 * U_];   // DP pb ring (slot = row & 15)
    __shared__ __align__(16) float se[16 * U_];   // DP pe ring

    const int bid = blockIdx.x;

    if (bid < N_) {
        if (threadIdx.x < 32)
            dp_warp(lengths, label_lengths, bid, threadIdx.x, sb, se, out);
        return;   // warps 1..3 exit immediately (no CTA-wide barriers in DP path)
    }

    // ---- gather row-task: task = bid-16 -> n = task%16, r = 1 + task/16 ----
    const int task = bid - N_;
    const int n = task & 15;
    const int r = 1 + (task >> 4);           // 1..383
    const int c = threadIdx.x;               // column 0..127

    const size_t rowbase = ((size_t)n * DD_PAD + r) * U_;

    int tb = r - 1 - c;                       // blank(t=tb, u=c)
    if (tb >= 0 && tb < T_) {
        float v = __ldcs(lp + ((((size_t)n * T_ + tb) * U_ + c) * V_) + (V_ - 1));
        g_pb[rowbase + c] = ex2_fast(v * LOG2E);
    }
    int te = r - c;                           // emit(t=te, u=c-1)
    if (c >= 1 && te >= 0 && te < T_) {
        int lbl = __ldg(&labels[n * (U_ - 1) + (c - 1)]);
        float v = __ldcs(lp + ((((size_t)n * T_ + te) * U_ + (c - 1)) * V_) + lbl);
        g_pe[rowbase + c] = ex2_fast(v * LOG2E);
    }

    __syncthreads();                          // orders all CTA stores before...
    if (c == 0) red_rel_add1(&g_rowflag[n * FLGS + r]);   // ...the row flag
}

// ---------------------------------------------------------------------------
extern "C" void kernel_launch(void* const* d_in, const int* in_sizes, int n_in,
                              void* d_out, int out_size)
{
    const float* log_probs     = (const float*)d_in[0];
    const int*   labels        = (const int*)  d_in[1];
    const int*   lengths       = (const int*)  d_in[2];
    const int*   label_lengths = (const int*)  d_in[3];
    float*       out           = (float*)d_out;

    fused_kernel<<<N_ + N_ * DD, U_>>>(log_probs, labels, lengths, label_lengths, out);
}

// round 17
// speedup vs baseline: 1.4869x; 1.4869x over previous
#include <cuda_runtime.h>
#include <cstdint>
#include <math.h>

// Problem shape (fixed): N=16, T=256, U=128, V=256, blank = V-1.
#define N_  16
#define T_  256
#define U_  128
#define V_  256
#define DD  383             // anti-diagonals d = 0..382
#define DD_PAD 400
#define LOG2E 1.4426950408889634f
#define LN2   0.6931471805599453f

// Scratch (allocation-free rule: __device__ globals, zero-initialized).
// SHIFTED diagonal-major PROBABILITIES: pb(n,t,u)=exp(blank lp) at
// [n][t+u+1][u]; pe(n,t,u)=exp(emit lp) at [n][t+u+1][u+1]. Unwritten slots
// stay 0.0 = impossible transition. Rows >= 384 are never written (read as 0).
__device__ __align__(16) float g_pb[N_ * DD_PAD * U_];
__device__ __align__(16) float g_pe[N_ * DD_PAD * U_];
__device__ float g_cost[N_];
// Epoch counters: +1 per launch each -> "flag >= ep" is reset-free across
// graph replays (R14-proven machinery).
__device__ unsigned g_costflag[N_];
__device__ unsigned g_dpep    [N_];

// ---- helpers ---------------------------------------------------------------
__device__ __forceinline__ float ex2_fast(float x) {
    float y; asm("ex2.approx.ftz.f32 %0, %1;" : "=f"(y) : "f"(x)); return y;
}
__device__ __forceinline__ unsigned ld_acq_u32(const unsigned* p) {
    unsigned v;
    asm volatile("ld.acquire.gpu.global.u32 %0, [%1];" : "=r"(v) : "l"(p) : "memory");
    return v;
}
__device__ __forceinline__ void red_rel_add1(unsigned* p) {
    asm volatile("red.release.gpu.global.add.u32 [%0], 1;" :: "l"(p) : "memory");
}

// ---------------------------------------------------------------------------
// Kernel 1: gather + exponentiate (UNCHANGED proven shape: 6128 tiny CTAs,
// coalesced writes, streaming scattered reads, ~5TB/s).
// ---------------------------------------------------------------------------
__global__ void __launch_bounds__(U_) gather_kernel(const float* __restrict__ lp,
                                                    const int*   __restrict__ labels)
{
    const int r = (blockIdx.x % DD) + 1;     // shifted row 1..383
    const int n = blockIdx.x / DD;
    const int c = threadIdx.x;               // column 0..127

    const size_t rowbase = ((size_t)n * DD_PAD + r) * U_;

    int tb = r - 1 - c;                       // blank(t=tb, u=c)
    if (tb >= 0 && tb < T_) {
        float v = __ldcs(lp + ((((size_t)n * T_ + tb) * U_ + c) * V_) + (V_ - 1));
        g_pb[rowbase + c] = ex2_fast(v * LOG2E);
    }
    int te = r - c;                           // emit(t=te, u=c-1)
    if (c >= 1 && te >= 0 && te < T_) {
        int lbl = __ldg(&labels[n * (U_ - 1) + (c - 1)]);
        float v = __ldcs(lp + ((((size_t)n * T_ + te) * U_ + (c - 1)) * V_) + lbl);
        g_pe[rowbase + c] = ex2_fast(v * LOG2E);
    }
}

// ---------------------------------------------------------------------------
// Kernel 2: linear-domain DP (R13 numerics) + folded finalize.
// One warp per example, 4 cols/lane, 16-slot cp.async smem ring.
// Strength-reduced addressing: running global pointers + rotating ring
// offsets. Rescale every 4 diagonals (was 2).
// ---------------------------------------------------------------------------
#define DP_STEP_MATH(bv, ev, dcur)                                            \
    {                                                                         \
        float la = __shfl_up_sync(0xffffffffu, a3, 1);                        \
        float l0 = (tx == 0) ? 0.0f : la;                                     \
        float n0 = fmaf(a0, (bv).x, l0 * (ev).x);                             \
        float n1 = fmaf(a1, (bv).y, a0 * (ev).y);                             \
        float n2 = fmaf(a2, (bv).z, a1 * (ev).z);                             \
        float n3 = fmaf(a3, (bv).w, a2 * (ev).w);                             \
        a0 = n0; a1 = n1; a2 = n2; a3 = n3;                                   \
        if ((dcur) == target && cap) {                                        \
            saved  = (ci == 0) ? n0 : (ci == 1) ? n1 : (ci == 2) ? n2 : n3;   \
            savedG = G;                                                       \
        }                                                                     \
    }

// One pair: waits, issues 2 rows via running pointers, computes 2 diagonals.
#define DP_PAIR()                                                             \
    {                                                                         \
        asm volatile("cp.async.wait_group 6;" ::: "memory");                  \
        asm volatile("cp.async.ca.shared.global [%0], [%1], 16;"              \
                     :: "r"(sb_base + wo), "l"(gbo));                         \
        asm volatile("cp.async.ca.shared.global [%0], [%1], 16;"              \
                     :: "r"(se_base + wo), "l"(geo));                         \
        asm volatile("cp.async.ca.shared.global [%0], [%1], 16;"              \
                     :: "r"(sb_base + we), "l"(gbe));                         \
        asm volatile("cp.async.ca.shared.global [%0], [%1], 16;"              \
                     :: "r"(se_base + we), "l"(gee));                         \
        asm volatile("cp.async.commit_group;" ::: "memory");                  \
        gbo += 2 * U_; gbe += 2 * U_; geo += 2 * U_; gee += 2 * U_;           \
        wo = (wo + 1024u) & 8191u; we = (we + 1024u) & 8191u;                 \
        {                                                                     \
            float4 b = *(const float4*)(sb + ro);                             \
            float4 e = *(const float4*)(se + ro);                             \
            DP_STEP_MATH(b, e, dd);                                           \
        }                                                                     \
        {                                                                     \
            float4 b = *(const float4*)(sb + re);                             \
            float4 e = *(const float4*)(se + re);                             \
            DP_STEP_MATH(b, e, dd + 1);                                       \
        }                                                                     \
        ro = (ro + 256) & 2047; re = (re + 256) & 2047;                       \
        dd += 2;                                                              \
    }

#define RESCALE_APPLY()                                                       \
    {                                                                         \
        int ef = (int)(mprev >> 23);                                          \
        int k  = 187 - ef;                                                    \
        k = k > 120 ? 120 : (k < -120 ? -120 : k);                            \
        float factor = __uint_as_float((unsigned)(127 + k) << 23);            \
        a0 *= factor; a1 *= factor; a2 *= factor; a3 *= factor;               \
        G += k;                                                               \
    }

#define RESCALE_MEASURE()                                                     \
    {                                                                         \
        float m = fmaxf(fmaxf(a0, a1), fmaxf(a2, a3));                        \
        mprev = __reduce_max_sync(0xffffffffu, __float_as_uint(m));           \
    }

// Prologue issue of one row (computed addressing; startup only).
#define ISSUE_ROW_ABS(rr)                                                     \
    {                                                                         \
        unsigned _slot = ((unsigned)(rr) & 15u) * (U_ * 4u) + lane_off;       \
        const float* _gb = bl + (size_t)(rr) * U_ + 4 * tx;                   \
        const float* _ge = em + (size_t)(rr) * U_ + 4 * tx;                   \
        asm volatile("cp.async.ca.shared.global [%0], [%1], 16;"              \
                     :: "r"(sb_base + _slot), "l"(_gb));                      \
        asm volatile("cp.async.ca.shared.global [%0], [%1], 16;"              \
                     :: "r"(se_base + _slot), "l"(_ge));                      \
    }

__global__ void __launch_bounds__(32) dp_kernel(const int* __restrict__ lengths,
                                                const int* __restrict__ label_lengths,
                                                float* __restrict__ out)
{
    __shared__ __align__(16) float sb[16 * U_];   // pb ring, slot = row & 15
    __shared__ __align__(16) float se[16 * U_];   // pe ring

    const int n  = blockIdx.x;
    const int tx = threadIdx.x;                   // owns u = 4*tx .. 4*tx+3

    unsigned ep;
    if (tx == 0) ep = atomicAdd(&g_dpep[n], 1u) + 1u;
    ep = __shfl_sync(0xffffffffu, ep, 0);

    const float* __restrict__ bl = g_pb + (size_t)n * DD_PAD * U_;
    const float* __restrict__ em = g_pe + (size_t)n * DD_PAD * U_;

    const int t_idx  = __ldg(&lengths[n]) - 1;
    const int u_idx  = __ldg(&label_lengths[n]);
    const int target = t_idx + u_idx;

    // alpha scaled by 2^G; seed alpha(0,0)=1 stored as 2^60 (window bias).
    float a0 = (tx == 0) ? __uint_as_float((127u + 60u) << 23) : 0.0f;
    float a1 = 0.0f, a2 = 0.0f, a3 = 0.0f;
    int   G = 60, savedG = 0;
    float saved = 1.0f;
    const bool cap = (tx == (u_idx >> 2));
    const int  ci  = u_idx & 3;

    const unsigned sb_base = (unsigned)__cvta_generic_to_shared(sb);
    const unsigned se_base = (unsigned)__cvta_generic_to_shared(se);
    const unsigned lane_off = 16u * (unsigned)tx;

    // Prologue: issue rows 1..14 (7 commit groups).
#pragma unroll
    for (int q = 0; q < 7; ++q) {
        ISSUE_ROW_ABS(2 * q + 1);
        ISSUE_ROW_ABS(2 * q + 2);
        asm volatile("cp.async.commit_group;" ::: "memory");
    }

    // Running state for the main loop.
    const float* gbo = bl + 15 * U_ + 4 * tx;   // odd-row pb source (15,17,..)
    const float* gbe = bl + 16 * U_ + 4 * tx;   // even-row pb source (16,18,..)
    const float* geo = em + 15 * U_ + 4 * tx;
    const float* gee = em + 16 * U_ + 4 * tx;
    unsigned wo = ((15u & 15u) * (U_ * 4u)) + lane_off;   // write byte offsets
    unsigned we = ((16u & 15u) * (U_ * 4u)) + lane_off;
    int ro = ((1 & 15) * U_) + 4 * tx;                    // read float offsets
    int re = ((2 & 15) * U_) + 4 * tx;
    int dd = 1;                                           // diagonal of step 1

    unsigned mprev = (127u + 60u) << 23;                  // k = 0 on first apply

    // 95 iterations x 2 pairs = diagonals 1..380; rescale once per 4 diagonals.
    for (int it = 0; it < 95; ++it) {
        RESCALE_APPLY();
        DP_PAIR();
        DP_PAIR();
        RESCALE_MEASURE();
    }
    RESCALE_APPLY();
    DP_PAIR();            // diagonals 381, 382

    if (cap) {
        float lpb_fin = __log2f(bl[(size_t)(target + 1) * U_ + u_idx]);
        float l2 = __log2f(saved) - (float)savedG + lpb_fin;
        g_cost[n] = -l2 * LN2;
        __threadfence();
        red_rel_add1(&g_costflag[n]);
    }

    // Folded finalize (CTA 0, lane 0): deterministic serial mean. All 16 CTAs
    // are co-resident at grid=16 and none waits on CTA 0 -> deadlock-free.
    if (n == 0 && tx == 0) {
        float s = 0.0f;
#pragma unroll
        for (int i = 0; i < N_; ++i) {
            while (ld_acq_u32(&g_costflag[i]) < ep) __nanosleep(128);
            s += __ldcg(&g_cost[i]);
        }
        out[0] = s * (1.0f / N_);
    }
}

// ---------------------------------------------------------------------------
// Launch: plain default-stream launches ONLY (streams/PDL fail the harness).
// ---------------------------------------------------------------------------
extern "C" void kernel_launch(void* const* d_in, const int* in_sizes, int n_in,
                              void* d_out, int out_size)
{
    const float* log_probs     = (const float*)d_in[0];
    const int*   labels        = (const int*)  d_in[1];
    const int*   lengths       = (const int*)  d_in[2];
    const int*   label_lengths = (const int*)  d_in[3];
    float*       out           = (float*)d_out;

    gather_kernel<<<N_ * DD, U_>>>(log_probs, labels);
    dp_kernel    <<<N_, 32>>>(lengths, label_lengths, out);
}